// round 2
// baseline (speedup 1.0000x reference)
#include <cuda_runtime.h>

#define B_  16
#define T_  512
#define K_  8
#define NI_ 256
#define UN_ 256
#define G_  1024   // 4*UNITS

// Scratch for the hoisted x@W + b projection: [B, T, K, 4U] fp32 = 268 MB.
__device__ float g_xw[(size_t)B_ * T_ * K_ * G_];

// ---------------------------------------------------------------------------
// Kernel 1: g_xw[m, k, :] = x[m, k, :] @ W[k] + b[k]   (m = b*T + t, 8192 rows)
// Classic 128x128 tile SGEMM, BK=8, 256 threads, 8x8 per-thread microtile.
// ---------------------------------------------------------------------------
__global__ __launch_bounds__(256) void gemm_xw_kernel(
    const float* __restrict__ x, const float* __restrict__ W,
    const float* __restrict__ bias)
{
    const int k  = blockIdx.z;
    const int bm = blockIdx.y * 128;
    const int bn = blockIdx.x * 128;

    __shared__ float As[8][128];   // transposed A tile: As[kk][row]
    __shared__ float Bs[8][128];

    const int tid  = threadIdx.x;
    const int arow = tid >> 1, acol = (tid & 1) * 4;   // A: 128 rows x 8 cols
    const int brow = tid >> 5, bcol = (tid & 31) * 4;  // B: 8 rows x 128 cols
    const int tx = tid & 15, ty = tid >> 4;

    float acc[8][8];
#pragma unroll
    for (int r = 0; r < 8; r++)
#pragma unroll
        for (int c = 0; c < 8; c++) acc[r][c] = 0.0f;

    // x row (b*T+t, k): offset ((m*K + k)*NI), contiguous NI floats
    const float* xA = x + ((size_t)(bm + arow) * K_ + k) * NI_;
    const float* wB = W + (size_t)k * NI_ * G_ + bn;

    for (int kt = 0; kt < NI_; kt += 8) {
        float4 av = *(const float4*)(xA + kt + acol);
        As[acol + 0][arow] = av.x;
        As[acol + 1][arow] = av.y;
        As[acol + 2][arow] = av.z;
        As[acol + 3][arow] = av.w;
        float4 bv = *(const float4*)(wB + (size_t)(kt + brow) * G_ + bcol);
        *(float4*)&Bs[brow][bcol] = bv;
        __syncthreads();
#pragma unroll
        for (int kk = 0; kk < 8; kk++) {
            float a[8], bb[8];
#pragma unroll
            for (int r = 0; r < 8; r++) a[r] = As[kk][ty * 8 + r];
#pragma unroll
            for (int c = 0; c < 8; c++) bb[c] = Bs[kk][tx * 8 + c];
#pragma unroll
            for (int r = 0; r < 8; r++)
#pragma unroll
                for (int c = 0; c < 8; c++)
                    acc[r][c] = fmaf(a[r], bb[c], acc[r][c]);
        }
        __syncthreads();
    }

    // Epilogue: add bias, store to scratch
#pragma unroll
    for (int r = 0; r < 8; r++) {
        const int m = bm + ty * 8 + r;
        float* orow = g_xw + ((size_t)m * K_ + k) * G_ + bn + tx * 8;
        const float* bs = bias + (size_t)k * G_ + bn + tx * 8;
#pragma unroll
        for (int c = 0; c < 8; c += 4) {
            float4 v;
            v.x = acc[r][c + 0] + bs[c + 0];
            v.y = acc[r][c + 1] + bs[c + 1];
            v.z = acc[r][c + 2] + bs[c + 2];
            v.w = acc[r][c + 3] + bs[c + 3];
            *(float4*)(orow + c) = v;
        }
    }
}

// ---------------------------------------------------------------------------
// Kernel 2: persistent recurrence. 64 blocks, each owns 2 (b,k) cells
// (same k, two b's) so each 1 MB U[k] read per step is amortized over 2 cells.
// 512 threads: thread jp handles gate columns j=2*jp, j=2*jp+1 for both b's
// (float2 U loads keep LDG-issue under the LSU floor).
// ---------------------------------------------------------------------------
__device__ __forceinline__ float hsig(float v) {
    return fminf(fmaxf(fmaf(v, 0.2f, 0.5f), 0.0f), 1.0f);
}

__global__ __launch_bounds__(512) void lstm_rec_kernel(
    const float* __restrict__ U, float* __restrict__ out)
{
    const int k  = blockIdx.x >> 3;   // 8 blocks per k
    const int bp = blockIdx.x & 7;
    const int b0 = bp * 2;

    __shared__ float sh_h[2][UN_];
    __shared__ float sh_c[2][UN_];
    __shared__ float sh_z[2][G_];

    const int tid = threadIdx.x;      // 0..511
    const int j   = tid * 2;

    for (int i = tid; i < 2 * UN_; i += 512) {
        (&sh_h[0][0])[i] = 0.0f;
        (&sh_c[0][0])[i] = 0.0f;
    }
    __syncthreads();

    const float* Uj  = U + (size_t)k * UN_ * G_ + j;
    const float* xw0 = g_xw + (((size_t)b0 * T_) * K_ + k) * G_;
    const float* xw1 = g_xw + (((size_t)(b0 + 1) * T_) * K_ + k) * G_;
    const size_t stepStride = (size_t)K_ * G_;   // 8192 floats per t

    for (int t = 0; t < T_; t++) {
        float2 a0 = *(const float2*)(xw0 + (size_t)t * stepStride + j);
        float2 a1 = *(const float2*)(xw1 + (size_t)t * stepStride + j);
        float acc00 = a0.x, acc01 = a0.y;
        float acc10 = a1.x, acc11 = a1.y;

#pragma unroll 8
        for (int i = 0; i < UN_; i++) {
            float2 uv = *(const float2*)(Uj + (size_t)i * G_);
            float h0 = sh_h[0][i];
            float h1 = sh_h[1][i];
            acc00 = fmaf(h0, uv.x, acc00);
            acc01 = fmaf(h0, uv.y, acc01);
            acc10 = fmaf(h1, uv.x, acc10);
            acc11 = fmaf(h1, uv.y, acc11);
        }

        sh_z[0][j]     = acc00;
        sh_z[0][j + 1] = acc01;
        sh_z[1][j]     = acc10;
        sh_z[1][j + 1] = acc11;
        __syncthreads();

        {   // 512 threads = 2 cells x 256 units: gate nonlinearities + state update
            const int bb = tid >> 8;
            const int u  = tid & 255;
            float av = tanhf(sh_z[bb][u]);
            float iv = hsig(sh_z[bb][UN_ + u]);
            float fv = hsig(sh_z[bb][2 * UN_ + u]);
            float ov = hsig(sh_z[bb][3 * UN_ + u]);
            float cn = fmaf(fv, sh_c[bb][u], av * iv);
            sh_c[bb][u] = cn;
            float hn = ov * tanhf(cn);
            sh_h[bb][u] = hn;
            out[(((size_t)(b0 + bb) * T_ + t) * K_ + k) * UN_ + u] = hn;
        }
        __syncthreads();
    }
}

// ---------------------------------------------------------------------------
extern "C" void kernel_launch(void* const* d_in, const int* in_sizes, int n_in,
                              void* d_out, int out_size)
{
    const float* x = (const float*)d_in[0];
    const float* W = (const float*)d_in[1];
    const float* U = (const float*)d_in[2];
    const float* b = (const float*)d_in[3];
    float* out = (float*)d_out;

    dim3 g1(G_ / 128, (B_ * T_) / 128, K_);   // 8 x 64 x 8
    gemm_xw_kernel<<<g1, 256>>>(x, W, b);

    lstm_rec_kernel<<<K_ * (B_ / 2), 512>>>(U, out);
}

// round 4
// speedup vs baseline: 3.5331x; 3.5331x over previous
#include <cuda_runtime.h>
#include <cuda_fp16.h>
#include <cstdint>

#define B_  16
#define T_  512
#define K_  8
#define NI_ 256
#define UN_ 256
#define G_  1024   // 4*UNITS

// Scratch for the hoisted x@W + b projection: [B, T, K, 4U] fp32 = 268 MB.
__device__ float g_xw[(size_t)B_ * T_ * K_ * G_];

// ---------------------------------------------------------------------------
// Kernel 1: g_xw[m, k, :] = x[m, k, :] @ W[k] + b[k]   (m = b*T + t, 8192 rows)
// ---------------------------------------------------------------------------
__global__ __launch_bounds__(256) void gemm_xw_kernel(
    const float* __restrict__ x, const float* __restrict__ W,
    const float* __restrict__ bias)
{
    const int k  = blockIdx.z;
    const int bm = blockIdx.y * 128;
    const int bn = blockIdx.x * 128;

    __shared__ float As[8][128];
    __shared__ float Bs[8][128];

    const int tid  = threadIdx.x;
    const int arow = tid >> 1, acol = (tid & 1) * 4;
    const int brow = tid >> 5, bcol = (tid & 31) * 4;
    const int tx = tid & 15, ty = tid >> 4;

    float acc[8][8];
#pragma unroll
    for (int r = 0; r < 8; r++)
#pragma unroll
        for (int c = 0; c < 8; c++) acc[r][c] = 0.0f;

    const float* xA = x + ((size_t)(bm + arow) * K_ + k) * NI_;
    const float* wB = W + (size_t)k * NI_ * G_ + bn;

    for (int kt = 0; kt < NI_; kt += 8) {
        float4 av = *(const float4*)(xA + kt + acol);
        As[acol + 0][arow] = av.x;
        As[acol + 1][arow] = av.y;
        As[acol + 2][arow] = av.z;
        As[acol + 3][arow] = av.w;
        float4 bv = *(const float4*)(wB + (size_t)(kt + brow) * G_ + bcol);
        *(float4*)&Bs[brow][bcol] = bv;
        __syncthreads();
#pragma unroll
        for (int kk = 0; kk < 8; kk++) {
            float a[8], bb[8];
#pragma unroll
            for (int r = 0; r < 8; r++) a[r] = As[kk][ty * 8 + r];
#pragma unroll
            for (int c = 0; c < 8; c++) bb[c] = Bs[kk][tx * 8 + c];
#pragma unroll
            for (int r = 0; r < 8; r++)
#pragma unroll
                for (int c = 0; c < 8; c++)
                    acc[r][c] = fmaf(a[r], bb[c], acc[r][c]);
        }
        __syncthreads();
    }

#pragma unroll
    for (int r = 0; r < 8; r++) {
        const int m = bm + ty * 8 + r;
        float* orow = g_xw + ((size_t)m * K_ + k) * G_ + bn + tx * 8;
        const float* bs = bias + (size_t)k * G_ + bn + tx * 8;
#pragma unroll
        for (int c = 0; c < 8; c += 4) {
            float4 v;
            v.x = acc[r][c + 0] + bs[c + 0];
            v.y = acc[r][c + 1] + bs[c + 1];
            v.z = acc[r][c + 2] + bs[c + 2];
            v.w = acc[r][c + 3] + bs[c + 3];
            *(float4*)(orow + c) = v;
        }
    }
}

// ---------------------------------------------------------------------------
// Kernel 2: warp-MMA recurrence. Cluster of 4 CTAs per k; CTA r owns units
// [64r, 64r+64) x all 4 gates: U^T slice [256 rows x 256 k] f16 in smem
// (rows padded to 264 halves = 528B for conflict-free ldmatrix).
// Per step: Z[16,256] = H[16,256] @ Uslice via mma.sync m16n8k16 (f32 acc),
// epilogue adds fp32 xw + activations, h broadcast to cluster via DSMEM
// into a double-buffered H tile.
// ---------------------------------------------------------------------------
__device__ __forceinline__ uint32_t smem_u32(const void* p) {
    uint32_t a;
    asm("{ .reg .u64 t; cvta.to.shared.u64 t, %1; cvt.u32.u64 %0, t; }" : "=r"(a) : "l"(p));
    return a;
}
__device__ __forceinline__ float hsig(float v) {
    return fminf(fmaxf(fmaf(v, 0.2f, 0.5f), 0.0f), 1.0f);
}

#define LDSM4(r0, r1, r2, r3, addr)                                        \
    asm volatile("ldmatrix.sync.aligned.m8n8.x4.shared.b16 {%0,%1,%2,%3}, [%4];" \
                 : "=r"(r0), "=r"(r1), "=r"(r2), "=r"(r3) : "r"(addr))

#define MMA16816(d, a0, a1, a2, a3, b0, b1)                                \
    asm volatile("mma.sync.aligned.m16n8k16.row.col.f32.f16.f16.f32 "      \
                 "{%0,%1,%2,%3}, {%4,%5,%6,%7}, {%8,%9}, {%0,%1,%2,%3};"   \
                 : "+f"(d[0]), "+f"(d[1]), "+f"(d[2]), "+f"(d[3])          \
                 : "r"(a0), "r"(a1), "r"(a2), "r"(a3), "r"(b0), "r"(b1))

// Row pitch: 264 halves (528 B). 528 mod 128 = 16 -> 8 consecutive rows hit
// 8 distinct 16B lanes: conflict-free ldmatrix.
#define UT_PITCH 264
#define H_PITCH  264
#define G_PITCH  68    // gates row pitch in floats (272 B)

#define OFF_UT 0                                  // 256 * 528 = 135168 B
#define OFF_H  (256 * UT_PITCH * 2)               // 2 bufs x 16 x 528 = 16896 B
#define OFF_G  (OFF_H + 2 * 16 * H_PITCH * 2)     // 4*16*68*4 = 17408 B
#define OFF_C  (OFF_G + 4 * 16 * G_PITCH * 4)     // 16*64*4 = 4096 B
#define SMEM_TOT (OFF_C + 16 * 64 * 4)

__global__ __launch_bounds__(256, 1) __cluster_dims__(4, 1, 1)
void lstm_rec_mma(const float* __restrict__ U, float* __restrict__ out)
{
    extern __shared__ char smem[];
    const uint32_t sb = smem_u32(smem);
    const int tid = threadIdx.x, w = tid >> 5, l = tid & 31;
    const int k = blockIdx.x >> 2;
    uint32_t rank;
    asm("mov.u32 %0, %%cluster_ctarank;" : "=r"(rank));

    // --- Load U^T slice: Ut[n_local][i] = U[k][i][g*256 + rank*64 + uloc],
    //     n_local = g*64 + uloc. Coalesced global reads (64-wide per gate).
    {
        const int g = tid >> 6, jloc = tid & 63;
        const float* up = U + (size_t)k * NI_ * G_ + g * 256 + (int)rank * 64 + jloc;
        half* uts = (half*)(smem + OFF_UT) + (size_t)(g * 64 + jloc) * UT_PITCH;
        for (int i = 0; i < 256; i++)
            uts[i] = __float2half_rn(up[(size_t)i * G_]);
    }
    // Zero both H buffers and c.
    for (int idx = tid; idx < 2 * 16 * H_PITCH; idx += 256)
        ((half*)(smem + OFF_H))[idx] = __float2half_rn(0.0f);
    for (int idx = tid; idx < 16 * 64; idx += 256)
        ((float*)(smem + OFF_C))[idx] = 0.0f;
    __syncthreads();
    asm volatile("barrier.cluster.arrive.aligned;" ::: "memory");
    asm volatile("barrier.cluster.wait.aligned;" ::: "memory");

    // Per-thread constant mapping.
    const int g    = w >> 1;                       // gate of this warp
    const int c_lo = l >> 2;                       // cell rows of d-frag
    const int j0loc = (w & 1) * 32 + (l & 3) * 2;  // uloc of d-frag col pair (nt=0)
    const float* xwb = g_xw + ((size_t)c_lo * T_ * K_ + k) * G_
                     + g * 256 + (int)rank * 64 + j0loc;
    const size_t XW_HI = (size_t)8 * T_ * K_ * G_;   // +8 cells
    float* gsm = (float*)(smem + OFF_G);
    float* csm = (float*)(smem + OFF_C);

    // ldmatrix source addresses (bytes).
    const uint32_t a_base0 = sb + OFF_H + (uint32_t)(l & 15) * (H_PITCH * 2)
                           + (uint32_t)(l >> 4) * 16;
    const uint32_t b_row   = (uint32_t)(w * 32 + ((l >> 4) << 3) + (l & 7));
    const uint32_t b_base0 = sb + OFF_UT + b_row * (UT_PITCH * 2)
                           + (uint32_t)((l >> 3) & 1) * 16;
    const uint32_t b_base1 = b_base0 + 16u * (UT_PITCH * 2);

    for (int t = 0; t < T_; t++) {
        // --- Prefetch xw (independent of MMA; hides DRAM/L2 latency) ---
        float2 xlo[4], xhi[4];
        const float* xwt = xwb + (size_t)t * (K_ * G_);
#pragma unroll
        for (int nt = 0; nt < 4; nt++) {
            xlo[nt] = __ldg((const float2*)(xwt + nt * 8));
            xhi[nt] = __ldg((const float2*)(xwt + XW_HI + nt * 8));
        }

        // --- MMA: Z[16, warp's 32 cols] over K=256 ---
        float acc[4][4];
#pragma unroll
        for (int nt = 0; nt < 4; nt++)
#pragma unroll
            for (int e = 0; e < 4; e++) acc[nt][e] = 0.0f;

        uint32_t aaddr = a_base0 + (uint32_t)(t & 1) * (16 * H_PITCH * 2);
        uint32_t baddr0 = b_base0, baddr1 = b_base1;
#pragma unroll
        for (int ks = 0; ks < 16; ks++) {
            uint32_t a0, a1, a2, a3, p0, p1, p2, p3, q0, q1, q2, q3;
            LDSM4(a0, a1, a2, a3, aaddr);
            LDSM4(p0, p1, p2, p3, baddr0);
            LDSM4(q0, q1, q2, q3, baddr1);
            MMA16816(acc[0], a0, a1, a2, a3, p0, p1);
            MMA16816(acc[1], a0, a1, a2, a3, p2, p3);
            MMA16816(acc[2], a0, a1, a2, a3, q0, q1);
            MMA16816(acc[3], a0, a1, a2, a3, q2, q3);
            aaddr += 32; baddr0 += 32; baddr1 += 32;
        }

        // --- Epilogue: z = acc + xw, activate, stage to gates smem ---
#pragma unroll
        for (int nt = 0; nt < 4; nt++) {
            const int uloc = j0loc + nt * 8;
            float z0 = acc[nt][0] + xlo[nt].x;
            float z1 = acc[nt][1] + xlo[nt].y;
            float z2 = acc[nt][2] + xhi[nt].x;
            float z3 = acc[nt][3] + xhi[nt].y;
            float v0, v1, v2, v3;
            if (g == 0) { v0 = tanhf(z0); v1 = tanhf(z1); v2 = tanhf(z2); v3 = tanhf(z3); }
            else        { v0 = hsig(z0);  v1 = hsig(z1);  v2 = hsig(z2);  v3 = hsig(z3); }
            *(float2*)(gsm + (size_t)(g * 16 + c_lo) * G_PITCH + uloc)
                = make_float2(v0, v1);
            *(float2*)(gsm + (size_t)(g * 16 + c_lo + 8) * G_PITCH + uloc)
                = make_float2(v2, v3);
        }
        __syncthreads();

        // --- State update: 512 (cell, u-pair) items over 2 iters ---
        const int wb = (t + 1) & 1;   // H write buffer
#pragma unroll
        for (int q = 0; q < 2; q++) {
            const int cell = q * 8 + w;
            const int u    = l * 2;
            float2 av = *(float2*)(gsm + (size_t)(0 * 16 + cell) * G_PITCH + u);
            float2 iv = *(float2*)(gsm + (size_t)(1 * 16 + cell) * G_PITCH + u);
            float2 fv = *(float2*)(gsm + (size_t)(2 * 16 + cell) * G_PITCH + u);
            float2 ov = *(float2*)(gsm + (size_t)(3 * 16 + cell) * G_PITCH + u);
            float2 cv = *(float2*)(csm + cell * 64 + u);
            float cn0 = fmaf(fv.x, cv.x, av.x * iv.x);
            float cn1 = fmaf(fv.y, cv.y, av.y * iv.y);
            *(float2*)(csm + cell * 64 + u) = make_float2(cn0, cn1);
            float h0 = ov.x * tanhf(cn0);
            float h1 = ov.y * tanhf(cn1);

            *(float2*)(out + (((size_t)cell * T_ + t) * K_ + k) * UN_
                       + (size_t)rank * 64 + u) = make_float2(h0, h1);

            __half2 hh = __floats2half2_rn(h0, h1);
            uint32_t hb = *(uint32_t*)&hh;
            uint32_t laddr = sb + OFF_H + (uint32_t)wb * (16 * H_PITCH * 2)
                           + (uint32_t)cell * (H_PITCH * 2)
                           + (rank * 64u + (uint32_t)u) * 2u;
#pragma unroll
            for (int peer = 0; peer < 4; peer++) {
                uint32_t ra;
                asm("mapa.shared::cluster.u32 %0, %1, %2;" : "=r"(ra) : "r"(laddr), "r"(peer));
                asm volatile("st.shared::cluster.b32 [%0], %1;" :: "r"(ra), "r"(hb) : "memory");
            }
        }

        // All peers' h writes visible before next step's ldmatrix.
        asm volatile("barrier.cluster.arrive.aligned;" ::: "memory");
        asm volatile("barrier.cluster.wait.aligned;" ::: "memory");
    }
}

// ---------------------------------------------------------------------------
extern "C" void kernel_launch(void* const* d_in, const int* in_sizes, int n_in,
                              void* d_out, int out_size)
{
    const float* x = (const float*)d_in[0];
    const float* W = (const float*)d_in[1];
    const float* U = (const float*)d_in[2];
    const float* b = (const float*)d_in[3];
    float* out = (float*)d_out;

    dim3 g1(G_ / 128, (B_ * T_) / 128, K_);
    gemm_xw_kernel<<<g1, 256>>>(x, W, b);

    cudaFuncSetAttribute(lstm_rec_mma, cudaFuncAttributeMaxDynamicSharedMemorySize, SMEM_TOT);
    lstm_rec_mma<<<K_ * 4, 256, SMEM_TOT>>>(U, out);
}